// round 13
// baseline (speedup 1.0000x reference)
#include <cuda_runtime.h>
#include <cstdint>

#define B_   64
#define T_   2048
#define DZ_  512
#define DC_  256
#define K_   12
#define R_   2
#define KO_  (K_ * DZ_)     // 6144

// score kernel: 4-deep 8KB ring, issue-early, one barrier/stage, 4 blocks/SM
#define RPB  256            // t' rows per block
#define THR  128
#define SDK  8              // d floats per pipeline stage (32 B per row)
#define NSTG (DZ_ / SDK)    // 64 stages
#define NBUF 4
#define STAGE_B 8192        // 256 rows x 32 B, swizzled, no padding
#define SCORE_SMEM (KO_ * 4 + NBUF * STAGE_B)     // 24576+32768=57344 -> 4 blocks/SM

// pred kernel: 32b x 32ko tiles, d pipelined in 4 chunks of 64, double-buffered
#define DCH   64            // d floats per chunk
#define NCH   (DC_ / DCH)   // 4 chunks
#define PCH   68            // chunk row pitch (floats)
#define CBUF  (2 * 32 * PCH)                       // floats per buffer (cts+ws)
#define PRED_SMEM (2 * CBUF * 4)                   // 34816 B

// ---- scratch (static device allocations; no cudaMalloc allowed) ----
__device__ __align__(16) float g_pred[B_ * KO_];   // [b][k*Dz+o]
__device__ __align__(16) float g_s[K_ * B_ * T_];  // [k][b][t']
__device__ unsigned long long g_acc;               // Q32.32 fixed-point loss accum
__device__ int g_cnt;

extern __shared__ __align__(16) float smem_dyn[];

static __device__ __forceinline__ unsigned smem_u32(const void* p) {
    return (unsigned)__cvta_generic_to_shared(p);
}
static __device__ __forceinline__ float u64lo(unsigned long long v) {
    return __uint_as_float((unsigned)(v & 0xffffffffu));
}
static __device__ __forceinline__ float u64hi(unsigned long long v) {
    return __uint_as_float((unsigned)(v >> 32));
}
// Swizzle for 32B-pitch rows: XOR 16B-group bits [4:6] with bits [7:9].
// Verified: each 8-lane LDS.128 phase hits 8 distinct 16B groups; keeps
// 16B alignment for cp.async destinations.
static __device__ __forceinline__ unsigned swz32(unsigned off) {
    return off ^ ((off >> 3) & 0x70u);
}

// ============================================================================
// Kernel A: pred[b][ko] = sum_d c[b, t[b], d] * W[ko][d] + bias[ko]
// GEMM 64 x 6144 x 256. 32b x 32ko tiles, 384 blocks (1 wave, 3/SM),
// d pipelined in 4 chunks of 64 via cp.async double buffer.
// ============================================================================
__global__ __launch_bounds__(256, 3) void pred_kernel(const float* __restrict__ c,
                                                      const float* __restrict__ W,
                                                      const float* __restrict__ bias,
                                                      const int*   __restrict__ t) {
    __shared__ int ts[32];

    int tid = threadIdx.x;
    if (blockIdx.x == 0 && tid == 0) { g_acc = 0ULL; g_cnt = 0; }

    int b0  = (blockIdx.x & 1) * 32;
    int ko0 = (blockIdx.x >> 1) * 32;

    if (tid < 32) ts[tid] = t[b0 + tid];
    __syncthreads();

    auto load_chunk = [&](int ch) {
        float* buf = smem_dyn + (ch & 1) * CBUF;
        unsigned cb = smem_u32(buf);
        unsigned wb = smem_u32(buf + 32 * PCH);
        int d0 = ch * DCH;
        #pragma unroll
        for (int i = 0; i < 2; i++) {
            int f = tid + i * 256;
            int r = f >> 4, c4 = f & 15;    // 32 rows x 16 float4
            const float* gc = c + ((long)(b0 + r) * T_ + ts[r]) * DC_ + d0 + c4 * 4;
            unsigned sc = cb + (unsigned)((r * PCH + c4 * 4) * 4);
            asm volatile("cp.async.cg.shared.global [%0], [%1], 16;\n"
                         :: "r"(sc), "l"(gc));
            const float* gw = W + (long)(ko0 + r) * DC_ + d0 + c4 * 4;
            unsigned sw = wb + (unsigned)((r * PCH + c4 * 4) * 4);
            asm volatile("cp.async.cg.shared.global [%0], [%1], 16;\n"
                         :: "r"(sw), "l"(gw));
        }
        asm volatile("cp.async.commit_group;\n");
    };

    load_chunk(0);
    load_chunk(1);

    int tx = tid & 15, ty = tid >> 4;      // tx: ko lane (16), ty: b lane (16)

    unsigned long long acc[2][2];
    acc[0][0] = acc[0][1] = acc[1][0] = acc[1][1] = 0ULL;

    for (int ch = 0; ch < NCH; ch++) {
        if (ch < NCH - 1) asm volatile("cp.async.wait_group 1;\n");
        else              asm volatile("cp.async.wait_group 0;\n");
        __syncthreads();

        const float* cts = smem_dyn + (ch & 1) * CBUF;
        const float* ws  = cts + 32 * PCH;

        #pragma unroll 4
        for (int d = 0; d < DCH; d += 4) {
            ulonglong2 cv[2], wv[2];
            #pragma unroll
            for (int i = 0; i < 2; i++)
                cv[i] = *(const ulonglong2*)(cts + (ty + 16 * i) * PCH + d);
            #pragma unroll
            for (int j = 0; j < 2; j++)
                wv[j] = *(const ulonglong2*)(ws + (tx + 16 * j) * PCH + d);
            #pragma unroll
            for (int i = 0; i < 2; i++)
                #pragma unroll
                for (int j = 0; j < 2; j++) {
                    asm("fma.rn.f32x2 %0, %1, %2, %0;"
                        : "+l"(acc[i][j]) : "l"(cv[i].x), "l"(wv[j].x));
                    asm("fma.rn.f32x2 %0, %1, %2, %0;"
                        : "+l"(acc[i][j]) : "l"(cv[i].y), "l"(wv[j].y));
                }
        }
        __syncthreads();
        if (ch + 2 < NCH) load_chunk(ch + 2);
    }

    #pragma unroll
    for (int i = 0; i < 2; i++) {
        int b = b0 + ty + 16 * i;
        #pragma unroll
        for (int j = 0; j < 2; j++) {
            int ko = ko0 + tx + 16 * j;
            g_pred[(long)b * KO_ + ko] =
                u64lo(acc[i][j]) + u64hi(acc[i][j]) + bias[ko];
        }
    }
}

// ============================================================================
// Kernel B (hot): s[k][b][t'] = dot(z[b,t',:], pred[b,k,:])
// z (268 MB) streamed once. NEW ring: NBUF=4 x 8KB swizzled stages,
// loads issued BEFORE compute, ONE barrier per stage (overwritten buffer's
// consumers all passed this stage's barrier). 4 blocks/SM, 1 wave.
// ============================================================================
__global__ __launch_bounds__(THR, 4) void score_kernel(const float* __restrict__ z) {
    float* preds = smem_dyn;                         // 6144 floats
    char*  zbuf  = (char*)(smem_dyn + KO_);          // 4 x 8KB swizzled stages

    const int tid  = threadIdx.x;
    const int b    = blockIdx.y;
    const int t0   = blockIdx.x * RPB;
    const int l    = tid & 31, w = tid >> 5;
    const int base = w * 64;

    const float* zb = z + ((long)b * T_ + t0) * DZ_;

    auto load_stage = [&](int s) {
        unsigned sb = smem_u32(zbuf + (s & (NBUF - 1)) * STAGE_B);
        const float* gs = zb + s * SDK;
        #pragma unroll
        for (int j = 0; j < 4; j++) {
            int f = tid + j * THR;                   // 0..511 16B slots
            int r = f >> 1, cc = f & 1;
            unsigned off = swz32((unsigned)(r * 32 + cc * 16));
            const float* ga = gs + (long)r * DZ_ + cc * 4;
            asm volatile("cp.async.cg.shared.global [%0], [%1], 16;\n"
                         :: "r"(sb + off), "l"(ga));
        }
        asm volatile("cp.async.commit_group;\n");
    };

    load_stage(0);
    load_stage(1);
    load_stage(2);

    // stage this b's 12 pred vectors (visible after the s=0 barrier)
    const float4* gp = (const float4*)(g_pred + (long)b * KO_);
    float4* sp = (float4*)preds;
    #pragma unroll
    for (int i = 0; i < KO_ / 4 / THR; i++) sp[tid + i * THR] = gp[tid + i * THR];

    unsigned long long acc[2][K_];
    #pragma unroll
    for (int i = 0; i < 2; i++)
        #pragma unroll
        for (int k = 0; k < K_; k++) acc[i][k] = 0ULL;

    for (int s = 0; s < NSTG; s++) {
        if (s < NSTG - 2)       asm volatile("cp.async.wait_group 2;\n");
        else if (s == NSTG - 2) asm volatile("cp.async.wait_group 1;\n");
        else                    asm volatile("cp.async.wait_group 0;\n");
        __syncthreads();           // stage s data visible to all warps

        if (s + 3 < NSTG) load_stage(s + 3);   // issue BEFORE compute

        const char* zc = zbuf + (s & (NBUF - 1)) * STAGE_B;
        #pragma unroll
        for (int c4 = 0; c4 < 2; c4++) {
            ulonglong2 zz[2];
            #pragma unroll
            for (int i = 0; i < 2; i++) {
                unsigned off = swz32((unsigned)((base + 32 * i + l) * 32 + c4 * 16));
                zz[i] = *(const ulonglong2*)(zc + off);
            }
            #pragma unroll
            for (int k = 0; k < K_; k++) {
                ulonglong2 p = *(const ulonglong2*)(preds + k * DZ_ + s * SDK + c4 * 4);
                #pragma unroll
                for (int i = 0; i < 2; i++) {
                    asm("fma.rn.f32x2 %0, %1, %2, %0;"
                        : "+l"(acc[i][k]) : "l"(zz[i].x), "l"(p.x));
                    asm("fma.rn.f32x2 %0, %1, %2, %0;"
                        : "+l"(acc[i][k]) : "l"(zz[i].y), "l"(p.y));
                }
            }
        }
    }

    #pragma unroll
    for (int i = 0; i < 2; i++) {
        int row = t0 + base + 32 * i + l;
        #pragma unroll
        for (int k = 0; k < K_; k++)
            g_s[((long)k * B_ + b) * T_ + row] = u64lo(acc[i][k]) + u64hi(acc[i][k]);
    }
}

// ============================================================================
// Kernel C: per (k,b) mean-over-replicates logsumexp. Global-max trick:
// one max pass, exp in place once, then each replicate = gather-and-sum.
// grid = 768 blocks, 256 threads.
// ============================================================================
__global__ __launch_bounds__(256) void loss_kernel(const int* __restrict__ t,
                                                   const int* __restrict__ ridx_g,
                                                   float* __restrict__ out) {
    __shared__ float srow[T_];
    __shared__ float red[8];

    int tid = threadIdx.x;
    int kb  = blockIdx.x;
    int k = kb >> 6, b = kb & 63;           // kb = k*B + b
    int lane = tid & 31, wid = tid >> 5;

    const float* src = g_s + (long)kb * T_;
    float m = -3.0e38f;
    float vals[8];
    #pragma unroll
    for (int i = 0; i < 8; i++) {
        float x = src[tid + i * 256];
        vals[i] = x;
        srow[tid + i * 256] = x;
        m = fmaxf(m, x);
    }
    __syncthreads();

    int e = t[b] + k + 1;
    float pos = srow[e];

    #pragma unroll
    for (int o = 16; o; o >>= 1) m = fmaxf(m, __shfl_xor_sync(0xffffffffu, m, o));
    if (lane == 0) red[wid] = m;
    __syncthreads();
    float M = red[0];
    #pragma unroll
    for (int j = 1; j < 8; j++) M = fmaxf(M, red[j]);
    __syncthreads();

    #pragma unroll
    for (int i = 0; i < 8; i++)
        srow[tid + i * 256] = __expf(vals[i] - M);
    __syncthreads();

    float epos = srow[e];
    float lse_sum = 0.f;

    #pragma unroll
    for (int r = 0; r < R_; r++) {
        const int* ridx = ridx_g + (k * R_ + r) * (T_ - 1);
        float sacc = (tid == 0) ? epos : 0.f;
        #pragma unroll
        for (int it = 0; it < 8; it++) {
            int i = tid + it * 256;
            if (i < T_ - 1) {
                int j = ridx[i];
                j += (j >= e);              // skip the positive frame
                sacc += srow[j];
            }
        }
        #pragma unroll
        for (int o = 16; o; o >>= 1) sacc += __shfl_xor_sync(0xffffffffu, sacc, o);
        if (lane == 0) red[wid] = sacc;
        __syncthreads();
        float ss = red[0];
        #pragma unroll
        for (int j = 1; j < 8; j++) ss += red[j];
        __syncthreads();

        lse_sum += M + __logf(ss);
    }

    if (tid == 0) {
        double vkb = (double)lse_sum / (double)R_ - (double)pos;   // >= 0
        long long q = __double2ll_rn(vkb * 4294967296.0);
        atomicAdd(&g_acc, (unsigned long long)q);
        __threadfence();
        if (atomicAdd(&g_cnt, 1) == K_ * B_ - 1) {
            unsigned long long tot = atomicAdd(&g_acc, 0ULL);
            out[0] = (float)((double)(long long)tot / 4294967296.0
                             / (double)(K_ * B_));
        }
    }
}

// ============================================================================
extern "C" void kernel_launch(void* const* d_in, const int* in_sizes, int n_in,
                              void* d_out, int out_size) {
    const float* z        = (const float*)d_in[0];
    const float* c        = (const float*)d_in[1];
    const float* Wk_w     = (const float*)d_in[2];
    const float* Wk_b     = (const float*)d_in[3];
    const int*   t        = (const int*)d_in[4];
    const int*   rand_idx = (const int*)d_in[5];

    cudaFuncSetAttribute(pred_kernel,
                         cudaFuncAttributeMaxDynamicSharedMemorySize, PRED_SMEM);
    cudaFuncSetAttribute(score_kernel,
                         cudaFuncAttributeMaxDynamicSharedMemorySize, SCORE_SMEM);

    pred_kernel<<<(KO_ / 32) * 2, 256, PRED_SMEM>>>(c, Wk_w, Wk_b, t);
    score_kernel<<<dim3(T_ / RPB, B_), THR, SCORE_SMEM>>>(z);
    loss_kernel<<<K_ * B_, 256>>>(t, rand_idx, (float*)d_out);
}

// round 14
// speedup vs baseline: 1.1220x; 1.1220x over previous
#include <cuda_runtime.h>
#include <cstdint>

#define B_   64
#define T_   2048
#define DZ_  512
#define DC_  256
#define K_   12
#define R_   2
#define KO_  (K_ * DZ_)     // 6144

// score kernel: 3-deep 16KB SW64 ring, single barrier/stage, issue-early
#define RPB  256            // t' rows per block
#define THR  128
#define SDK  16             // d floats per pipeline stage (64 B per row)
#define NSTG (DZ_ / SDK)    // 32 stages
#define NBUF 3
#define STAGE_B 16384       // 256 rows x 64 B, SW64 swizzle, no padding
#define SCORE_SMEM (KO_ * 4 + NBUF * STAGE_B)     // 24576+49152=73728 -> 3 blocks/SM

// pred kernel: 32b x 32ko tiles, d pipelined in 4 chunks of 64, double-buffered
#define DCH   64            // d floats per chunk
#define NCH   (DC_ / DCH)   // 4 chunks
#define PCH   68            // chunk row pitch (floats)
#define CBUF  (2 * 32 * PCH)                       // floats per buffer (cts+ws)
#define PRED_SMEM (2 * CBUF * 4)                   // 34816 B

// ---- scratch (static device allocations; no cudaMalloc allowed) ----
__device__ __align__(16) float g_pred[B_ * KO_];   // [b][k*Dz+o]
__device__ __align__(16) float g_s[K_ * B_ * T_];  // [k][b][t']
__device__ unsigned long long g_acc;               // Q32.32 fixed-point loss accum
__device__ int g_cnt;

extern __shared__ __align__(16) float smem_dyn[];

static __device__ __forceinline__ unsigned smem_u32(const void* p) {
    return (unsigned)__cvta_generic_to_shared(p);
}
static __device__ __forceinline__ float u64lo(unsigned long long v) {
    return __uint_as_float((unsigned)(v & 0xffffffffu));
}
static __device__ __forceinline__ float u64hi(unsigned long long v) {
    return __uint_as_float((unsigned)(v >> 32));
}
// SW64-style swizzle for 64B-pitch rows (XOR bits 4-5 with 7-8):
// conflict-free 16B accesses, preserves 16B alignment.
static __device__ __forceinline__ unsigned swz64(unsigned off) {
    return off ^ ((off >> 3) & 0x30u);
}

// ============================================================================
// Kernel A: pred[b][ko] = sum_d c[b, t[b], d] * W[ko][d] + bias[ko]
// GEMM 64 x 6144 x 256. 32b x 32ko tiles, 384 blocks (1 wave, 3/SM),
// d pipelined in 4 chunks of 64 via cp.async double buffer.  [R13, 16.4us]
// ============================================================================
__global__ __launch_bounds__(256, 3) void pred_kernel(const float* __restrict__ c,
                                                      const float* __restrict__ W,
                                                      const float* __restrict__ bias,
                                                      const int*   __restrict__ t) {
    __shared__ int ts[32];

    int tid = threadIdx.x;
    if (blockIdx.x == 0 && tid == 0) { g_acc = 0ULL; g_cnt = 0; }

    int b0  = (blockIdx.x & 1) * 32;
    int ko0 = (blockIdx.x >> 1) * 32;

    if (tid < 32) ts[tid] = t[b0 + tid];
    __syncthreads();

    auto load_chunk = [&](int ch) {
        float* buf = smem_dyn + (ch & 1) * CBUF;
        unsigned cb = smem_u32(buf);
        unsigned wb = smem_u32(buf + 32 * PCH);
        int d0 = ch * DCH;
        #pragma unroll
        for (int i = 0; i < 2; i++) {
            int f = tid + i * 256;
            int r = f >> 4, c4 = f & 15;    // 32 rows x 16 float4
            const float* gc = c + ((long)(b0 + r) * T_ + ts[r]) * DC_ + d0 + c4 * 4;
            unsigned sc = cb + (unsigned)((r * PCH + c4 * 4) * 4);
            asm volatile("cp.async.cg.shared.global [%0], [%1], 16;\n"
                         :: "r"(sc), "l"(gc));
            const float* gw = W + (long)(ko0 + r) * DC_ + d0 + c4 * 4;
            unsigned sw = wb + (unsigned)((r * PCH + c4 * 4) * 4);
            asm volatile("cp.async.cg.shared.global [%0], [%1], 16;\n"
                         :: "r"(sw), "l"(gw));
        }
        asm volatile("cp.async.commit_group;\n");
    };

    load_chunk(0);
    load_chunk(1);

    int tx = tid & 15, ty = tid >> 4;      // tx: ko lane (16), ty: b lane (16)

    unsigned long long acc[2][2];
    acc[0][0] = acc[0][1] = acc[1][0] = acc[1][1] = 0ULL;

    for (int ch = 0; ch < NCH; ch++) {
        if (ch < NCH - 1) asm volatile("cp.async.wait_group 1;\n");
        else              asm volatile("cp.async.wait_group 0;\n");
        __syncthreads();

        const float* cts = smem_dyn + (ch & 1) * CBUF;
        const float* ws  = cts + 32 * PCH;

        #pragma unroll 4
        for (int d = 0; d < DCH; d += 4) {
            ulonglong2 cv[2], wv[2];
            #pragma unroll
            for (int i = 0; i < 2; i++)
                cv[i] = *(const ulonglong2*)(cts + (ty + 16 * i) * PCH + d);
            #pragma unroll
            for (int j = 0; j < 2; j++)
                wv[j] = *(const ulonglong2*)(ws + (tx + 16 * j) * PCH + d);
            #pragma unroll
            for (int i = 0; i < 2; i++)
                #pragma unroll
                for (int j = 0; j < 2; j++) {
                    asm("fma.rn.f32x2 %0, %1, %2, %0;"
                        : "+l"(acc[i][j]) : "l"(cv[i].x), "l"(wv[j].x));
                    asm("fma.rn.f32x2 %0, %1, %2, %0;"
                        : "+l"(acc[i][j]) : "l"(cv[i].y), "l"(wv[j].y));
                }
        }
        __syncthreads();
        if (ch + 2 < NCH) load_chunk(ch + 2);
    }

    #pragma unroll
    for (int i = 0; i < 2; i++) {
        int b = b0 + ty + 16 * i;
        #pragma unroll
        for (int j = 0; j < 2; j++) {
            int ko = ko0 + tx + 16 * j;
            g_pred[(long)b * KO_ + ko] =
                u64lo(acc[i][j]) + u64hi(acc[i][j]) + bias[ko];
        }
    }
}

// ============================================================================
// Kernel B (hot): s[k][b][t'] = dot(z[b,t',:], pred[b,k,:])
// z (268 MB) streamed once. NBUF=3 x 16KB SW64 stages, wait_group 1,
// ONE barrier per stage, loads issued right after the barrier
// (overwritten buffer held stage s-1, fully consumed before this barrier).
// Committed in-flight: 2 stages x 16KB x 3 blocks = 96KB/SM.
// ============================================================================
__global__ __launch_bounds__(THR, 3) void score_kernel(const float* __restrict__ z) {
    float* preds = smem_dyn;                         // 6144 floats
    char*  zbuf  = (char*)(smem_dyn + KO_);          // 3 x 16KB swizzled stages

    const int tid  = threadIdx.x;
    const int b    = blockIdx.y;
    const int t0   = blockIdx.x * RPB;
    const int l    = tid & 31, w = tid >> 5;
    const int base = w * 64;

    const float* zb = z + ((long)b * T_ + t0) * DZ_;

    auto load_stage = [&](int s) {
        int bufsel = s % NBUF;
        unsigned sb = smem_u32(zbuf + bufsel * STAGE_B);
        const float* gs = zb + s * SDK;
        #pragma unroll
        for (int j = 0; j < 8; j++) {
            int f = tid + j * THR;                   // 0..1023 16B slots
            int r = f >> 2, cc = f & 3;
            unsigned off = swz64((unsigned)(r * 64 + cc * 16));
            const float* ga = gs + (long)r * DZ_ + cc * 4;
            asm volatile("cp.async.cg.shared.global [%0], [%1], 16;\n"
                         :: "r"(sb + off), "l"(ga));
        }
        asm volatile("cp.async.commit_group;\n");
    };

    load_stage(0);
    load_stage(1);

    // stage this b's 12 pred vectors (ordered by the s=0 barrier)
    const float4* gp = (const float4*)(g_pred + (long)b * KO_);
    float4* sp = (float4*)preds;
    #pragma unroll
    for (int i = 0; i < KO_ / 4 / THR; i++) sp[tid + i * THR] = gp[tid + i * THR];

    unsigned long long acc[2][K_];
    #pragma unroll
    for (int i = 0; i < 2; i++)
        #pragma unroll
        for (int k = 0; k < K_; k++) acc[i][k] = 0ULL;

    for (int s = 0; s < NSTG; s++) {
        if (s < NSTG - 1) asm volatile("cp.async.wait_group 1;\n");
        else              asm volatile("cp.async.wait_group 0;\n");
        __syncthreads();           // stage s visible; stage s-1 consumers done

        if (s + 2 < NSTG) load_stage(s + 2);   // issue BEFORE compute

        const char* zc = zbuf + (s % NBUF) * STAGE_B;
        #pragma unroll
        for (int c4 = 0; c4 < 4; c4++) {
            ulonglong2 zz[2];
            #pragma unroll
            for (int i = 0; i < 2; i++) {
                unsigned off = swz64((unsigned)((base + 32 * i + l) * 64 + c4 * 16));
                zz[i] = *(const ulonglong2*)(zc + off);
            }
            #pragma unroll
            for (int k = 0; k < K_; k++) {
                ulonglong2 p = *(const ulonglong2*)(preds + k * DZ_ + s * SDK + c4 * 4);
                #pragma unroll
                for (int i = 0; i < 2; i++) {
                    asm("fma.rn.f32x2 %0, %1, %2, %0;"
                        : "+l"(acc[i][k]) : "l"(zz[i].x), "l"(p.x));
                    asm("fma.rn.f32x2 %0, %1, %2, %0;"
                        : "+l"(acc[i][k]) : "l"(zz[i].y), "l"(p.y));
                }
            }
        }
    }

    #pragma unroll
    for (int i = 0; i < 2; i++) {
        int row = t0 + base + 32 * i + l;
        #pragma unroll
        for (int k = 0; k < K_; k++)
            g_s[((long)k * B_ + b) * T_ + row] = u64lo(acc[i][k]) + u64hi(acc[i][k]);
    }
}

// ============================================================================
// Kernel C: per (k,b) mean-over-replicates logsumexp. Global-max trick +
// FUSED replicates: both gathers in one pass, both sums in one barrier round.
// grid = 768 blocks, 256 threads.
// ============================================================================
__global__ __launch_bounds__(256) void loss_kernel(const int* __restrict__ t,
                                                   const int* __restrict__ ridx_g,
                                                   float* __restrict__ out) {
    __shared__ float srow[T_];
    __shared__ float red0[8];
    __shared__ float red1[8];

    int tid = threadIdx.x;
    int kb  = blockIdx.x;
    int k = kb >> 6, b = kb & 63;           // kb = k*B + b
    int lane = tid & 31, wid = tid >> 5;

    const float* src = g_s + (long)kb * T_;
    float m = -3.0e38f;
    float vals[8];
    #pragma unroll
    for (int i = 0; i < 8; i++) {
        float x = src[tid + i * 256];
        vals[i] = x;
        srow[tid + i * 256] = x;
        m = fmaxf(m, x);
    }
    __syncthreads();

    int e = t[b] + k + 1;
    float pos = srow[e];

    #pragma unroll
    for (int o = 16; o; o >>= 1) m = fmaxf(m, __shfl_xor_sync(0xffffffffu, m, o));
    if (lane == 0) red0[wid] = m;
    __syncthreads();
    float M = red0[0];
    #pragma unroll
    for (int j = 1; j < 8; j++) M = fmaxf(M, red0[j]);
    __syncthreads();

    #pragma unroll
    for (int i = 0; i < 8; i++)
        srow[tid + i * 256] = __expf(vals[i] - M);
    __syncthreads();

    float epos = srow[e];

    const int* ridx0 = ridx_g + (k * R_ + 0) * (T_ - 1);
    const int* ridx1 = ridx_g + (k * R_ + 1) * (T_ - 1);
    float s0 = (tid == 0) ? epos : 0.f;
    float s1 = s0;
    #pragma unroll
    for (int it = 0; it < 8; it++) {
        int i = tid + it * 256;
        if (i < T_ - 1) {
            int j0 = ridx0[i]; j0 += (j0 >= e);
            int j1 = ridx1[i]; j1 += (j1 >= e);
            s0 += srow[j0];
            s1 += srow[j1];
        }
    }
    #pragma unroll
    for (int o = 16; o; o >>= 1) {
        s0 += __shfl_xor_sync(0xffffffffu, s0, o);
        s1 += __shfl_xor_sync(0xffffffffu, s1, o);
    }
    if (lane == 0) { red0[wid] = s0; red1[wid] = s1; }
    __syncthreads();

    if (tid == 0) {
        float ss0 = red0[0], ss1 = red1[0];
        #pragma unroll
        for (int j = 1; j < 8; j++) { ss0 += red0[j]; ss1 += red1[j]; }
        float lse_sum = 2.f * M + __logf(ss0) + __logf(ss1);

        double vkb = (double)lse_sum / (double)R_ - (double)pos;   // >= 0
        long long q = __double2ll_rn(vkb * 4294967296.0);
        atomicAdd(&g_acc, (unsigned long long)q);
        __threadfence();
        if (atomicAdd(&g_cnt, 1) == K_ * B_ - 1) {
            unsigned long long tot = atomicAdd(&g_acc, 0ULL);
            out[0] = (float)((double)(long long)tot / 4294967296.0
                             / (double)(K_ * B_));
        }
    }
}

// ============================================================================
extern "C" void kernel_launch(void* const* d_in, const int* in_sizes, int n_in,
                              void* d_out, int out_size) {
    const float* z        = (const float*)d_in[0];
    const float* c        = (const float*)d_in[1];
    const float* Wk_w     = (const float*)d_in[2];
    const float* Wk_b     = (const float*)d_in[3];
    const int*   t        = (const int*)d_in[4];
    const int*   rand_idx = (const int*)d_in[5];

    cudaFuncSetAttribute(pred_kernel,
                         cudaFuncAttributeMaxDynamicSharedMemorySize, PRED_SMEM);
    cudaFuncSetAttribute(score_kernel,
                         cudaFuncAttributeMaxDynamicSharedMemorySize, SCORE_SMEM);

    pred_kernel<<<(KO_ / 32) * 2, 256, PRED_SMEM>>>(c, Wk_w, Wk_b, t);
    score_kernel<<<dim3(T_ / RPB, B_), THR, SCORE_SMEM>>>(z);
    loss_kernel<<<K_ * B_, 256>>>(t, rand_idx, (float*)d_out);
}

// round 15
// speedup vs baseline: 1.1755x; 1.0476x over previous
#include <cuda_runtime.h>
#include <cstdint>

#define B_   64
#define T_   2048
#define DZ_  512
#define DC_  256
#define K_   12
#define R_   2
#define KO_  (K_ * DZ_)     // 6144

// score kernel: R12-pinned config. 16KB SW64 stages, double buffer,
// 2 barriers/stage, 4 blocks/SM, grid 512 = one wave.
#define RPB  256            // t' rows per block
#define THR  128
#define SDK  16             // d floats per pipeline stage (64 B per row)
#define NSTG (DZ_ / SDK)    // 32 stages
#define STAGE_B 16384       // 256 rows x 64 B, SW64 swizzle, no padding
#define SCORE_SMEM (KO_ * 4 + 2 * STAGE_B)         // 57344 -> 4 blocks/SM

// pred kernel: 32b x 32ko tiles, d pipelined in 4 chunks of 64, double-buffered
#define DCH   64            // d floats per chunk
#define NCH   (DC_ / DCH)   // 4 chunks
#define PCH   68            // chunk row pitch (floats)
#define CBUF  (2 * 32 * PCH)                       // floats per buffer (cts+ws)
#define PRED_SMEM (2 * CBUF * 4)                   // 34816 B

// ---- scratch (static device allocations; no cudaMalloc allowed) ----
__device__ __align__(16) float g_pred[B_ * KO_];   // [b][k*Dz+o]
__device__ __align__(16) float g_s[K_ * B_ * T_];  // [k][b][t']
__device__ unsigned long long g_acc;               // Q32.32 fixed-point loss accum
__device__ int g_cnt;

extern __shared__ __align__(16) float smem_dyn[];

static __device__ __forceinline__ unsigned smem_u32(const void* p) {
    return (unsigned)__cvta_generic_to_shared(p);
}
static __device__ __forceinline__ float u64lo(unsigned long long v) {
    return __uint_as_float((unsigned)(v & 0xffffffffu));
}
static __device__ __forceinline__ float u64hi(unsigned long long v) {
    return __uint_as_float((unsigned)(v >> 32));
}
// SW64-style swizzle for 64B-pitch rows (XOR bits 4-5 with 7-8):
// conflict-free 16B accesses, preserves 16B alignment.
static __device__ __forceinline__ unsigned swz64(unsigned off) {
    return off ^ ((off >> 3) & 0x30u);
}

// ============================================================================
// Kernel A: pred[b][ko] = sum_d c[b, t[b], d] * W[ko][d] + bias[ko]
// GEMM 64 x 6144 x 256. 32b x 32ko tiles, 384 blocks (1 wave, 3/SM),
// d pipelined in 4 chunks of 64 via cp.async double buffer.  [16.2us measured]
// ============================================================================
__global__ __launch_bounds__(256, 3) void pred_kernel(const float* __restrict__ c,
                                                      const float* __restrict__ W,
                                                      const float* __restrict__ bias,
                                                      const int*   __restrict__ t) {
    __shared__ int ts[32];

    int tid = threadIdx.x;
    if (blockIdx.x == 0 && tid == 0) { g_acc = 0ULL; g_cnt = 0; }

    int b0  = (blockIdx.x & 1) * 32;
    int ko0 = (blockIdx.x >> 1) * 32;

    if (tid < 32) ts[tid] = t[b0 + tid];
    __syncthreads();

    auto load_chunk = [&](int ch) {
        float* buf = smem_dyn + (ch & 1) * CBUF;
        unsigned cb = smem_u32(buf);
        unsigned wb = smem_u32(buf + 32 * PCH);
        int d0 = ch * DCH;
        #pragma unroll
        for (int i = 0; i < 2; i++) {
            int f = tid + i * 256;
            int r = f >> 4, c4 = f & 15;    // 32 rows x 16 float4
            const float* gc = c + ((long)(b0 + r) * T_ + ts[r]) * DC_ + d0 + c4 * 4;
            unsigned sc = cb + (unsigned)((r * PCH + c4 * 4) * 4);
            asm volatile("cp.async.cg.shared.global [%0], [%1], 16;\n"
                         :: "r"(sc), "l"(gc));
            const float* gw = W + (long)(ko0 + r) * DC_ + d0 + c4 * 4;
            unsigned sw = wb + (unsigned)((r * PCH + c4 * 4) * 4);
            asm volatile("cp.async.cg.shared.global [%0], [%1], 16;\n"
                         :: "r"(sw), "l"(gw));
        }
        asm volatile("cp.async.commit_group;\n");
    };

    load_chunk(0);
    load_chunk(1);

    int tx = tid & 15, ty = tid >> 4;      // tx: ko lane (16), ty: b lane (16)

    unsigned long long acc[2][2];
    acc[0][0] = acc[0][1] = acc[1][0] = acc[1][1] = 0ULL;

    for (int ch = 0; ch < NCH; ch++) {
        if (ch < NCH - 1) asm volatile("cp.async.wait_group 1;\n");
        else              asm volatile("cp.async.wait_group 0;\n");
        __syncthreads();

        const float* cts = smem_dyn + (ch & 1) * CBUF;
        const float* ws  = cts + 32 * PCH;

        #pragma unroll 4
        for (int d = 0; d < DCH; d += 4) {
            ulonglong2 cv[2], wv[2];
            #pragma unroll
            for (int i = 0; i < 2; i++)
                cv[i] = *(const ulonglong2*)(cts + (ty + 16 * i) * PCH + d);
            #pragma unroll
            for (int j = 0; j < 2; j++)
                wv[j] = *(const ulonglong2*)(ws + (tx + 16 * j) * PCH + d);
            #pragma unroll
            for (int i = 0; i < 2; i++)
                #pragma unroll
                for (int j = 0; j < 2; j++) {
                    asm("fma.rn.f32x2 %0, %1, %2, %0;"
                        : "+l"(acc[i][j]) : "l"(cv[i].x), "l"(wv[j].x));
                    asm("fma.rn.f32x2 %0, %1, %2, %0;"
                        : "+l"(acc[i][j]) : "l"(cv[i].y), "l"(wv[j].y));
                }
        }
        __syncthreads();
        if (ch + 2 < NCH) load_chunk(ch + 2);
    }

    #pragma unroll
    for (int i = 0; i < 2; i++) {
        int b = b0 + ty + 16 * i;
        #pragma unroll
        for (int j = 0; j < 2; j++) {
            int ko = ko0 + tx + 16 * j;
            g_pred[(long)b * KO_ + ko] =
                u64lo(acc[i][j]) + u64hi(acc[i][j]) + bias[ko];
        }
    }
}

// ============================================================================
// Kernel B (hot): s[k][b][t'] = dot(z[b,t',:], pred[b,k,:])
// EXACT R12 config (57.8us measured; best of 6 variants):
// 2 x 16KB SW64 stages, wait-bar-compute-bar-load, 4 blocks/SM, one wave.
// ============================================================================
__global__ __launch_bounds__(THR, 4) void score_kernel(const float* __restrict__ z) {
    float* preds = smem_dyn;                         // 6144 floats
    char*  zbuf  = (char*)(smem_dyn + KO_);          // 2 x 16KB swizzled stages

    const int tid  = threadIdx.x;
    const int b    = blockIdx.y;
    const int t0   = blockIdx.x * RPB;
    const int l    = tid & 31, w = tid >> 5;
    const int base = w * 64;

    const float* zb = z + ((long)b * T_ + t0) * DZ_;

    auto load_stage = [&](int s, int bufsel) {
        unsigned sb = smem_u32(zbuf + bufsel * STAGE_B);
        const float* gs = zb + s * SDK;
        #pragma unroll
        for (int j = 0; j < 8; j++) {
            int f = tid + j * THR;                   // 0..1023 16B slots
            int r = f >> 2, cc = f & 3;
            unsigned off = swz64((unsigned)(r * 64 + cc * 16));
            const float* ga = gs + (long)r * DZ_ + cc * 4;
            asm volatile("cp.async.cg.shared.global [%0], [%1], 16;\n"
                         :: "r"(sb + off), "l"(ga));
        }
        asm volatile("cp.async.commit_group;\n");
    };

    load_stage(0, 0);
    load_stage(1, 1);

    // stage this b's 12 pred vectors
    const float4* gp = (const float4*)(g_pred + (long)b * KO_);
    float4* sp = (float4*)preds;
    #pragma unroll
    for (int i = 0; i < KO_ / 4 / THR; i++) sp[tid + i * THR] = gp[tid + i * THR];

    unsigned long long acc[2][K_];
    #pragma unroll
    for (int i = 0; i < 2; i++)
        #pragma unroll
        for (int k = 0; k < K_; k++) acc[i][k] = 0ULL;

    for (int s = 0; s < NSTG; s++) {
        if (s < NSTG - 1) asm volatile("cp.async.wait_group 1;\n");
        else              asm volatile("cp.async.wait_group 0;\n");
        __syncthreads();

        const char* zc = zbuf + (s & 1) * STAGE_B;
        #pragma unroll
        for (int c4 = 0; c4 < 4; c4++) {
            ulonglong2 zz[2];
            #pragma unroll
            for (int i = 0; i < 2; i++) {
                unsigned off = swz64((unsigned)((base + 32 * i + l) * 64 + c4 * 16));
                zz[i] = *(const ulonglong2*)(zc + off);
            }
            #pragma unroll
            for (int k = 0; k < K_; k++) {
                ulonglong2 p = *(const ulonglong2*)(preds + k * DZ_ + s * SDK + c4 * 4);
                #pragma unroll
                for (int i = 0; i < 2; i++) {
                    asm("fma.rn.f32x2 %0, %1, %2, %0;"
                        : "+l"(acc[i][k]) : "l"(zz[i].x), "l"(p.x));
                    asm("fma.rn.f32x2 %0, %1, %2, %0;"
                        : "+l"(acc[i][k]) : "l"(zz[i].y), "l"(p.y));
                }
            }
        }
        __syncthreads();
        if (s + 2 < NSTG) load_stage(s + 2, s & 1);
    }

    #pragma unroll
    for (int i = 0; i < 2; i++) {
        int row = t0 + base + 32 * i + l;
        #pragma unroll
        for (int k = 0; k < K_; k++)
            g_s[((long)k * B_ + b) * T_ + row] = u64lo(acc[i][k]) + u64hi(acc[i][k]);
    }
}

// ============================================================================
// Kernel C: per (k,b) mean-over-replicates logsumexp. Global-max trick +
// fused replicates (both gathers one pass, both sums one barrier round).
// grid = 768 blocks, 256 threads.
// ============================================================================
__global__ __launch_bounds__(256) void loss_kernel(const int* __restrict__ t,
                                                   const int* __restrict__ ridx_g,
                                                   float* __restrict__ out) {
    __shared__ float srow[T_];
    __shared__ float red0[8];
    __shared__ float red1[8];

    int tid = threadIdx.x;
    int kb  = blockIdx.x;
    int k = kb >> 6, b = kb & 63;           // kb = k*B + b
    int lane = tid & 31, wid = tid >> 5;

    const float* src = g_s + (long)kb * T_;
    float m = -3.0e38f;
    float vals[8];
    #pragma unroll
    for (int i = 0; i < 8; i++) {
        float x = src[tid + i * 256];
        vals[i] = x;
        srow[tid + i * 256] = x;
        m = fmaxf(m, x);
    }
    __syncthreads();

    int e = t[b] + k + 1;
    float pos = srow[e];

    #pragma unroll
    for (int o = 16; o; o >>= 1) m = fmaxf(m, __shfl_xor_sync(0xffffffffu, m, o));
    if (lane == 0) red0[wid] = m;
    __syncthreads();
    float M = red0[0];
    #pragma unroll
    for (int j = 1; j < 8; j++) M = fmaxf(M, red0[j]);
    __syncthreads();

    #pragma unroll
    for (int i = 0; i < 8; i++)
        srow[tid + i * 256] = __expf(vals[i] - M);
    __syncthreads();

    float epos = srow[e];

    const int* ridx0 = ridx_g + (k * R_ + 0) * (T_ - 1);
    const int* ridx1 = ridx_g + (k * R_ + 1) * (T_ - 1);
    float s0 = (tid == 0) ? epos : 0.f;
    float s1 = s0;
    #pragma unroll
    for (int it = 0; it < 8; it++) {
        int i = tid + it * 256;
        if (i < T_ - 1) {
            int j0 = ridx0[i]; j0 += (j0 >= e);
            int j1 = ridx1[i]; j1 += (j1 >= e);
            s0 += srow[j0];
            s1 += srow[j1];
        }
    }
    #pragma unroll
    for (int o = 16; o; o >>= 1) {
        s0 += __shfl_xor_sync(0xffffffffu, s0, o);
        s1 += __shfl_xor_sync(0xffffffffu, s1, o);
    }
    if (lane == 0) { red0[wid] = s0; red1[wid] = s1; }
    __syncthreads();

    if (tid == 0) {
        float ss0 = red0[0], ss1 = red1[0];
        #pragma unroll
        for (int j = 1; j < 8; j++) { ss0 += red0[j]; ss1 += red1[j]; }
        float lse_sum = 2.f * M + __logf(ss0) + __logf(ss1);

        double vkb = (double)lse_sum / (double)R_ - (double)pos;   // >= 0
        long long q = __double2ll_rn(vkb * 4294967296.0);
        atomicAdd(&g_acc, (unsigned long long)q);
        __threadfence();
        if (atomicAdd(&g_cnt, 1) == K_ * B_ - 1) {
            unsigned long long tot = atomicAdd(&g_acc, 0ULL);
            out[0] = (float)((double)(long long)tot / 4294967296.0
                             / (double)(K_ * B_));
        }
    }
}

// ============================================================================
extern "C" void kernel_launch(void* const* d_in, const int* in_sizes, int n_in,
                              void* d_out, int out_size) {
    const float* z        = (const float*)d_in[0];
    const float* c        = (const float*)d_in[1];
    const float* Wk_w     = (const float*)d_in[2];
    const float* Wk_b     = (const float*)d_in[3];
    const int*   t        = (const int*)d_in[4];
    const int*   rand_idx = (const int*)d_in[5];

    cudaFuncSetAttribute(pred_kernel,
                         cudaFuncAttributeMaxDynamicSharedMemorySize, PRED_SMEM);
    cudaFuncSetAttribute(score_kernel,
                         cudaFuncAttributeMaxDynamicSharedMemorySize, SCORE_SMEM);

    pred_kernel<<<(KO_ / 32) * 2, 256, PRED_SMEM>>>(c, Wk_w, Wk_b, t);
    score_kernel<<<dim3(T_ / RPB, B_), THR, SCORE_SMEM>>>(z);
    loss_kernel<<<K_ * B_, 256>>>(t, rand_idx, (float*)d_out);
}